// round 15
// baseline (speedup 1.0000x reference)
#include <cuda_runtime.h>
#include <math.h>

// SLAYFeatures R15 = R14 with a 3-stage in-thread pipeline over row batches
// (3,3,2): batch k's stores (512B bursts) interleave into batch k+1's
// accumulate loop; only the last 2 rows' stores are exposed at the tail.
// out[b, r*8192 + h*512 + p*32 + m] = poly[b,h,p] * prf[b,r,h,m]

#define NB 8
#define THREADS 256

__global__ __launch_bounds__(THREADS, 3) void slay_kernel(
    const float* __restrict__ x,        // [8192,1024]
    const float* __restrict__ omega,    // [2,16,64,32]
    const float* __restrict__ anchors,  // [16,64]
    float* __restrict__ out,            // [8192,16384]
    float s0, float s1, float c0, float c1, float e0, float e1)
{
    __shared__ __align__(16) float xs[NB][1024];   // normalized x rows (32 KB)
    __shared__ __align__(16) float poly[NB][256];  // [b][h*16+p]        (8 KB)
    __shared__ float an_t[64][17];                 // anchors^T, padded  (4.25 KB)

    const int t  = threadIdx.x;
    const int b0 = blockIdx.x * NB;

    // ---------- Phase 0: stage anchors transposed ----------
    {
#pragma unroll
        for (int i = 0; i < 4; i++) {
            int idx = i * 256 + t;          // anchors[p][d]
            an_t[idx & 63][idx >> 6] = anchors[idx];
        }
    }

    // ---------- Phase 1: load x, per-head normalize ----------
    {
        float4 v[NB];
        float  ss[NB];
        const float4* x4 = (const float4*)x;
#pragma unroll
        for (int k = 0; k < NB; k++) {
            v[k] = x4[(size_t)(b0 + k) * 256 + t];
            ss[k] = v[k].x*v[k].x + v[k].y*v[k].y + v[k].z*v[k].z + v[k].w*v[k].w;
        }
#pragma unroll
        for (int k = 0; k < NB; k++) {
#pragma unroll
            for (int off = 8; off; off >>= 1)
                ss[k] += __shfl_xor_sync(0xffffffffu, ss[k], off);
            float inv = 1.0f / (sqrtf(fmaxf(ss[k], 1e-12f)) + 1e-4f);
            float4 w = v[k];
            w.x *= inv; w.y *= inv; w.z *= inv; w.w *= inv;
            ((float4*)xs[k])[t] = w;
        }
    }
    __syncthreads();

    // ---------- Phase 2: poly features (anchors from smem) ----------
    {
        const int h = t >> 4, p = t & 15;
        float acc[NB];
#pragma unroll
        for (int k = 0; k < NB; k++) acc[k] = 0.0f;
#pragma unroll 4
        for (int d4 = 0; d4 < 16; d4++) {
            float ax = an_t[d4 * 4 + 0][p];
            float ay = an_t[d4 * 4 + 1][p];
            float az = an_t[d4 * 4 + 2][p];
            float aw = an_t[d4 * 4 + 3][p];
#pragma unroll
            for (int k = 0; k < NB; k++) {
                float4 xv = ((const float4*)xs[k])[h * 16 + d4];
                acc[k] += xv.x*ax + xv.y*ay + xv.z*az + xv.w*aw;
            }
        }
#pragma unroll
        for (int k = 0; k < NB; k++)
            poly[k][t] = acc[k] * acc[k] * 0.25f;
    }
    __syncthreads();

    // ---------- Phase 3: 3-stage pipelined PRF + 512B-burst stores ----------
    {
        const int r  = t >> 7;
        const int h  = (t >> 3) & 15;
        const int m4 = t & 7;
        const float sr = r ? s1 : s0;
        const float cr = r ? c1 : c0;
        const float er = r ? e1 : e0;
        const float4* og = (const float4*)omega + (size_t)((r * 16 + h) * 64) * 8 + m4;
        const size_t obase = r * 8192 + h * 512 + m4 * 4;

        float4 pr0[3], pr1[3];

        // ---- Batch 0: rows 0..2 compute ----
        {
            float4 acc[3];
#pragma unroll
            for (int k = 0; k < 3; k++) acc[k] = make_float4(0.f, 0.f, 0.f, 0.f);
#pragma unroll 4
            for (int d4 = 0; d4 < 16; d4++) {
                float4 o0 = og[(4 * d4 + 0) * 8];
                float4 o1 = og[(4 * d4 + 1) * 8];
                float4 o2 = og[(4 * d4 + 2) * 8];
                float4 o3 = og[(4 * d4 + 3) * 8];
#pragma unroll
                for (int k = 0; k < 3; k++) {
                    float4 xv = ((const float4*)xs[k])[h * 16 + d4];
                    acc[k].x += xv.x*o0.x; acc[k].y += xv.x*o0.y; acc[k].z += xv.x*o0.z; acc[k].w += xv.x*o0.w;
                    acc[k].x += xv.y*o1.x; acc[k].y += xv.y*o1.y; acc[k].z += xv.y*o1.z; acc[k].w += xv.y*o1.w;
                    acc[k].x += xv.z*o2.x; acc[k].y += xv.z*o2.y; acc[k].z += xv.z*o2.z; acc[k].w += xv.z*o2.w;
                    acc[k].x += xv.w*o3.x; acc[k].y += xv.w*o3.y; acc[k].z += xv.w*o3.z; acc[k].w += xv.w*o3.w;
                }
            }
#pragma unroll
            for (int k = 0; k < 3; k++) {
                float4 a = acc[k];
                pr0[k].x = er * __expf(fminf(fmaxf(a.x * cr - sr, -20.f), 20.f));
                pr0[k].y = er * __expf(fminf(fmaxf(a.y * cr - sr, -20.f), 20.f));
                pr0[k].z = er * __expf(fminf(fmaxf(a.z * cr - sr, -20.f), 20.f));
                pr0[k].w = er * __expf(fminf(fmaxf(a.w * cr - sr, -20.f), 20.f));
            }
        }

        // ---- Batch 1: rows 3..5 compute, batch 0 stores interleaved ----
        {
            float4 acc[3];
#pragma unroll
            for (int k = 0; k < 3; k++) acc[k] = make_float4(0.f, 0.f, 0.f, 0.f);
#pragma unroll
            for (int d4 = 0; d4 < 16; d4++) {
                float4 o0 = og[(4 * d4 + 0) * 8];
                float4 o1 = og[(4 * d4 + 1) * 8];
                float4 o2 = og[(4 * d4 + 2) * 8];
                float4 o3 = og[(4 * d4 + 3) * 8];
#pragma unroll
                for (int k = 0; k < 3; k++) {
                    float4 xv = ((const float4*)xs[3 + k])[h * 16 + d4];
                    acc[k].x += xv.x*o0.x; acc[k].y += xv.x*o0.y; acc[k].z += xv.x*o0.z; acc[k].w += xv.x*o0.w;
                    acc[k].x += xv.y*o1.x; acc[k].y += xv.y*o1.y; acc[k].z += xv.y*o1.z; acc[k].w += xv.y*o1.w;
                    acc[k].x += xv.z*o2.x; acc[k].y += xv.z*o2.y; acc[k].z += xv.z*o2.z; acc[k].w += xv.z*o2.w;
                    acc[k].x += xv.w*o3.x; acc[k].y += xv.w*o3.y; acc[k].z += xv.w*o3.z; acc[k].w += xv.w*o3.w;
                }
                if (d4 < 12) {  // 12 bursts: row = d4>>2 (0..2), p0 = (d4&3)*4
                    const int k  = d4 >> 2;
                    const int p0 = (d4 & 3) * 4;
                    float* ob = out + (size_t)(b0 + k) * 16384 + obase;
                    const float* pl = &poly[k][h * 16];
                    float4 pa = pr0[k];
#pragma unroll
                    for (int pp = 0; pp < 4; pp++) {
                        float pf = pl[p0 + pp];
                        float4 o;
                        o.x = pf * pa.x; o.y = pf * pa.y; o.z = pf * pa.z; o.w = pf * pa.w;
                        __stcs((float4*)(ob + (p0 + pp) * 32), o);
                    }
                }
            }
#pragma unroll
            for (int k = 0; k < 3; k++) {
                float4 a = acc[k];
                pr1[k].x = er * __expf(fminf(fmaxf(a.x * cr - sr, -20.f), 20.f));
                pr1[k].y = er * __expf(fminf(fmaxf(a.y * cr - sr, -20.f), 20.f));
                pr1[k].z = er * __expf(fminf(fmaxf(a.z * cr - sr, -20.f), 20.f));
                pr1[k].w = er * __expf(fminf(fmaxf(a.w * cr - sr, -20.f), 20.f));
            }
        }

        // ---- Batch 2: rows 6..7 compute, batch 1 stores interleaved ----
        {
            float4 acc[2];
#pragma unroll
            for (int k = 0; k < 2; k++) acc[k] = make_float4(0.f, 0.f, 0.f, 0.f);
#pragma unroll
            for (int d4 = 0; d4 < 16; d4++) {
                float4 o0 = og[(4 * d4 + 0) * 8];
                float4 o1 = og[(4 * d4 + 1) * 8];
                float4 o2 = og[(4 * d4 + 2) * 8];
                float4 o3 = og[(4 * d4 + 3) * 8];
#pragma unroll
                for (int k = 0; k < 2; k++) {
                    float4 xv = ((const float4*)xs[6 + k])[h * 16 + d4];
                    acc[k].x += xv.x*o0.x; acc[k].y += xv.x*o0.y; acc[k].z += xv.x*o0.z; acc[k].w += xv.x*o0.w;
                    acc[k].x += xv.y*o1.x; acc[k].y += xv.y*o1.y; acc[k].z += xv.y*o1.z; acc[k].w += xv.y*o1.w;
                    acc[k].x += xv.z*o2.x; acc[k].y += xv.z*o2.y; acc[k].z += xv.z*o2.z; acc[k].w += xv.z*o2.w;
                    acc[k].x += xv.w*o3.x; acc[k].y += xv.w*o3.y; acc[k].z += xv.w*o3.z; acc[k].w += xv.w*o3.w;
                }
                if (d4 < 12) {  // batch 1: rows 3..5
                    const int k  = d4 >> 2;
                    const int p0 = (d4 & 3) * 4;
                    float* ob = out + (size_t)(b0 + 3 + k) * 16384 + obase;
                    const float* pl = &poly[3 + k][h * 16];
                    float4 pa = pr1[k];
#pragma unroll
                    for (int pp = 0; pp < 4; pp++) {
                        float pf = pl[p0 + pp];
                        float4 o;
                        o.x = pf * pa.x; o.y = pf * pa.y; o.z = pf * pa.z; o.w = pf * pa.w;
                        __stcs((float4*)(ob + (p0 + pp) * 32), o);
                    }
                }
            }
            // exp + tail stores for rows 6..7 (8 bursts)
#pragma unroll
            for (int k = 0; k < 2; k++) {
                float4 a = acc[k];
                float4 pr;
                pr.x = er * __expf(fminf(fmaxf(a.x * cr - sr, -20.f), 20.f));
                pr.y = er * __expf(fminf(fmaxf(a.y * cr - sr, -20.f), 20.f));
                pr.z = er * __expf(fminf(fmaxf(a.z * cr - sr, -20.f), 20.f));
                pr.w = er * __expf(fminf(fmaxf(a.w * cr - sr, -20.f), 20.f));

                float* ob = out + (size_t)(b0 + 6 + k) * 16384 + obase;
                const float* pl = &poly[6 + k][h * 16];
#pragma unroll
                for (int p = 0; p < 16; p++) {
                    float pf = pl[p];
                    float4 o;
                    o.x = pf * pr.x; o.y = pf * pr.y; o.z = pf * pr.z; o.w = pf * pr.w;
                    __stcs((float4*)(ob + p * 32), o);
                }
            }
        }
    }
}

extern "C" void kernel_launch(void* const* d_in, const int* in_sizes, int n_in,
                              void* d_out, int out_size) {
    const float* x       = (const float*)d_in[0];
    const float* omega   = (const float*)d_in[1];
    const float* anchors = (const float*)d_in[2];
    float* out = (float*)d_out;

    const double C   = 2.0 + 1e-6;
    const double rt2 = 1.4142135623730951;
    const double n0d = 2.0 - rt2, n1d = 2.0 + rt2;
    const double w0d = (2.0 + rt2) / 4.0, w1d = (2.0 - rt2) / 4.0;

    float s0 = (float)(n0d / C);
    float s1 = (float)(n1d / C);
    float c0 = sqrtf(2.0f * s0);
    float c1 = sqrtf(2.0f * s1);
    float invSqrtM = 1.0f / sqrtf(32.0f);
    float e0 = sqrtf((float)(w0d / C)) * invSqrtM;
    float e1 = sqrtf((float)(w1d / C)) * invSqrtM;

    slay_kernel<<<8192 / NB, THREADS>>>(x, omega, anchors, out,
                                        s0, s1, c0, c1, e0, e1);
    (void)in_sizes; (void)n_in; (void)out_size;
}

// round 16
// speedup vs baseline: 1.8336x; 1.8336x over previous
#include <cuda_runtime.h>
#include <math.h>

// SLAYFeatures R16 = R14 with asymmetric 6/2 batch split in phase 3:
// batch A (rows 0..5) computes first; batch B (rows 6..7) computes while
// draining ALL 24 of A's 512B store bursts (2/iter for 8 iters, then 1/iter);
// only B's 8 bursts/thread remain exposed at the tail (was 16 in R14).
// out[b, r*8192 + h*512 + p*32 + m] = poly[b,h,p] * prf[b,r,h,m]

#define NB 8
#define THREADS 256

__global__ __launch_bounds__(THREADS, 3) void slay_kernel(
    const float* __restrict__ x,        // [8192,1024]
    const float* __restrict__ omega,    // [2,16,64,32]
    const float* __restrict__ anchors,  // [16,64]
    float* __restrict__ out,            // [8192,16384]
    float s0, float s1, float c0, float c1, float e0, float e1)
{
    __shared__ __align__(16) float xs[NB][1024];   // normalized x rows (32 KB)
    __shared__ __align__(16) float poly[NB][256];  // [b][h*16+p]        (8 KB)
    __shared__ float an_t[64][17];                 // anchors^T, padded  (4.25 KB)

    const int t  = threadIdx.x;
    const int b0 = blockIdx.x * NB;

    // ---------- Phase 0: stage anchors transposed ----------
    {
#pragma unroll
        for (int i = 0; i < 4; i++) {
            int idx = i * 256 + t;          // anchors[p][d]
            an_t[idx & 63][idx >> 6] = anchors[idx];
        }
    }

    // ---------- Phase 1: load x, per-head normalize ----------
    {
        float4 v[NB];
        float  ss[NB];
        const float4* x4 = (const float4*)x;
#pragma unroll
        for (int k = 0; k < NB; k++) {
            v[k] = x4[(size_t)(b0 + k) * 256 + t];
            ss[k] = v[k].x*v[k].x + v[k].y*v[k].y + v[k].z*v[k].z + v[k].w*v[k].w;
        }
#pragma unroll
        for (int k = 0; k < NB; k++) {
#pragma unroll
            for (int off = 8; off; off >>= 1)
                ss[k] += __shfl_xor_sync(0xffffffffu, ss[k], off);
            float inv = 1.0f / (sqrtf(fmaxf(ss[k], 1e-12f)) + 1e-4f);
            float4 w = v[k];
            w.x *= inv; w.y *= inv; w.z *= inv; w.w *= inv;
            ((float4*)xs[k])[t] = w;
        }
    }
    __syncthreads();

    // ---------- Phase 2: poly features (anchors from smem) ----------
    {
        const int h = t >> 4, p = t & 15;
        float acc[NB];
#pragma unroll
        for (int k = 0; k < NB; k++) acc[k] = 0.0f;
#pragma unroll 4
        for (int d4 = 0; d4 < 16; d4++) {
            float ax = an_t[d4 * 4 + 0][p];
            float ay = an_t[d4 * 4 + 1][p];
            float az = an_t[d4 * 4 + 2][p];
            float aw = an_t[d4 * 4 + 3][p];
#pragma unroll
            for (int k = 0; k < NB; k++) {
                float4 xv = ((const float4*)xs[k])[h * 16 + d4];
                acc[k] += xv.x*ax + xv.y*ay + xv.z*az + xv.w*aw;
            }
        }
#pragma unroll
        for (int k = 0; k < NB; k++)
            poly[k][t] = acc[k] * acc[k] * 0.25f;
    }
    __syncthreads();

    // ---------- Phase 3: 6/2 batch-split PRF + interleaved 512B bursts ----------
    {
        const int r  = t >> 7;
        const int h  = (t >> 3) & 15;
        const int m4 = t & 7;
        const float sr = r ? s1 : s0;
        const float cr = r ? c1 : c0;
        const float er = r ? e1 : e0;
        const float4* og = (const float4*)omega + (size_t)((r * 16 + h) * 64) * 8 + m4;
        const size_t obase = r * 8192 + h * 512 + m4 * 4;

        // ---- Batch A: rows 0..5 accumulate ----
        float4 prA[6];
        {
            float4 acc[6];
#pragma unroll
            for (int k = 0; k < 6; k++) acc[k] = make_float4(0.f, 0.f, 0.f, 0.f);
#pragma unroll 4
            for (int d4 = 0; d4 < 16; d4++) {
                float4 o0 = og[(4 * d4 + 0) * 8];
                float4 o1 = og[(4 * d4 + 1) * 8];
                float4 o2 = og[(4 * d4 + 2) * 8];
                float4 o3 = og[(4 * d4 + 3) * 8];
#pragma unroll
                for (int k = 0; k < 6; k++) {
                    float4 xv = ((const float4*)xs[k])[h * 16 + d4];
                    acc[k].x += xv.x*o0.x; acc[k].y += xv.x*o0.y; acc[k].z += xv.x*o0.z; acc[k].w += xv.x*o0.w;
                    acc[k].x += xv.y*o1.x; acc[k].y += xv.y*o1.y; acc[k].z += xv.y*o1.z; acc[k].w += xv.y*o1.w;
                    acc[k].x += xv.z*o2.x; acc[k].y += xv.z*o2.y; acc[k].z += xv.z*o2.z; acc[k].w += xv.z*o2.w;
                    acc[k].x += xv.w*o3.x; acc[k].y += xv.w*o3.y; acc[k].z += xv.w*o3.z; acc[k].w += xv.w*o3.w;
                }
            }
#pragma unroll
            for (int k = 0; k < 6; k++) {
                float4 a = acc[k];
                prA[k].x = er * __expf(fminf(fmaxf(a.x * cr - sr, -20.f), 20.f));
                prA[k].y = er * __expf(fminf(fmaxf(a.y * cr - sr, -20.f), 20.f));
                prA[k].z = er * __expf(fminf(fmaxf(a.z * cr - sr, -20.f), 20.f));
                prA[k].w = er * __expf(fminf(fmaxf(a.w * cr - sr, -20.f), 20.f));
            }
        }

        // ---- Batch B: rows 6..7 accumulate; A's 24 bursts interleaved ----
        {
            float4 acc[2];
#pragma unroll
            for (int k = 0; k < 2; k++) acc[k] = make_float4(0.f, 0.f, 0.f, 0.f);

#pragma unroll
            for (int d4 = 0; d4 < 16; d4++) {
                float4 o0 = og[(4 * d4 + 0) * 8];
                float4 o1 = og[(4 * d4 + 1) * 8];
                float4 o2 = og[(4 * d4 + 2) * 8];
                float4 o3 = og[(4 * d4 + 3) * 8];
#pragma unroll
                for (int k = 0; k < 2; k++) {
                    float4 xv = ((const float4*)xs[6 + k])[h * 16 + d4];
                    acc[k].x += xv.x*o0.x; acc[k].y += xv.x*o0.y; acc[k].z += xv.x*o0.z; acc[k].w += xv.x*o0.w;
                    acc[k].x += xv.y*o1.x; acc[k].y += xv.y*o1.y; acc[k].z += xv.y*o1.z; acc[k].w += xv.y*o1.w;
                    acc[k].x += xv.z*o2.x; acc[k].y += xv.z*o2.y; acc[k].z += xv.z*o2.z; acc[k].w += xv.z*o2.w;
                    acc[k].x += xv.w*o3.x; acc[k].y += xv.w*o3.y; acc[k].z += xv.w*o3.z; acc[k].w += xv.w*o3.w;
                }
                // bursts (compile-time schedule): iters 0..7 -> 2 bursts, 8..15 -> 1
#pragma unroll
                for (int j = 0; j < 2; j++) {
                    if (d4 < 8 || j == 0) {
                        const int bi = (d4 < 8) ? (2 * d4 + j) : (16 + (d4 - 8));  // 0..23
                        const int k  = bi >> 2;          // row 0..5
                        const int p0 = (bi & 3) * 4;     // consecutive p in time per row
                        float* ob = out + (size_t)(b0 + k) * 16384 + obase;
                        const float* pl = &poly[k][h * 16];
                        float4 pa = prA[k];
#pragma unroll
                        for (int pp = 0; pp < 4; pp++) {
                            float pf = pl[p0 + pp];
                            float4 o;
                            o.x = pf * pa.x; o.y = pf * pa.y; o.z = pf * pa.z; o.w = pf * pa.w;
                            __stcs((float4*)(ob + (p0 + pp) * 32), o);
                        }
                    }
                }
            }

            // exp + tail stores for rows 6..7 (8 bursts exposed)
#pragma unroll
            for (int k = 0; k < 2; k++) {
                float4 a = acc[k];
                float4 pr;
                pr.x = er * __expf(fminf(fmaxf(a.x * cr - sr, -20.f), 20.f));
                pr.y = er * __expf(fminf(fmaxf(a.y * cr - sr, -20.f), 20.f));
                pr.z = er * __expf(fminf(fmaxf(a.z * cr - sr, -20.f), 20.f));
                pr.w = er * __expf(fminf(fmaxf(a.w * cr - sr, -20.f), 20.f));

                float* ob = out + (size_t)(b0 + 6 + k) * 16384 + obase;
                const float* pl = &poly[6 + k][h * 16];
#pragma unroll
                for (int p = 0; p < 16; p++) {
                    float pf = pl[p];
                    float4 o;
                    o.x = pf * pr.x; o.y = pf * pr.y; o.z = pf * pr.z; o.w = pf * pr.w;
                    __stcs((float4*)(ob + p * 32), o);
                }
            }
        }
    }
}

extern "C" void kernel_launch(void* const* d_in, const int* in_sizes, int n_in,
                              void* d_out, int out_size) {
    const float* x       = (const float*)d_in[0];
    const float* omega   = (const float*)d_in[1];
    const float* anchors = (const float*)d_in[2];
    float* out = (float*)d_out;

    const double C   = 2.0 + 1e-6;
    const double rt2 = 1.4142135623730951;
    const double n0d = 2.0 - rt2, n1d = 2.0 + rt2;
    const double w0d = (2.0 + rt2) / 4.0, w1d = (2.0 - rt2) / 4.0;

    float s0 = (float)(n0d / C);
    float s1 = (float)(n1d / C);
    float c0 = sqrtf(2.0f * s0);
    float c1 = sqrtf(2.0f * s1);
    float invSqrtM = 1.0f / sqrtf(32.0f);
    float e0 = sqrtf((float)(w0d / C)) * invSqrtM;
    float e1 = sqrtf((float)(w1d / C)) * invSqrtM;

    slay_kernel<<<8192 / NB, THREADS>>>(x, omega, anchors, out,
                                        s0, s1, c0, c1, e0, e1);
    (void)in_sizes; (void)n_in; (void)out_size;
}

// round 17
// speedup vs baseline: 1.8400x; 1.0035x over previous
#include <cuda_runtime.h>
#include <math.h>

// SLAYFeatures R17 = R16 with 7/1 batch split in phase 3:
// batch A (rows 0..6) computes, then batch B (row 7) computes while draining
// ALL 28 of A's 512B store bursts; only B's 4 bursts remain exposed.
// out[b, r*8192 + h*512 + p*32 + m] = poly[b,h,p] * prf[b,r,h,m]

#define NB 8
#define THREADS 256

__global__ __launch_bounds__(THREADS, 3) void slay_kernel(
    const float* __restrict__ x,        // [8192,1024]
    const float* __restrict__ omega,    // [2,16,64,32]
    const float* __restrict__ anchors,  // [16,64]
    float* __restrict__ out,            // [8192,16384]
    float s0, float s1, float c0, float c1, float e0, float e1)
{
    __shared__ __align__(16) float xs[NB][1024];   // normalized x rows (32 KB)
    __shared__ __align__(16) float poly[NB][256];  // [b][h*16+p]        (8 KB)
    __shared__ float an_t[64][17];                 // anchors^T, padded  (4.25 KB)

    const int t  = threadIdx.x;
    const int b0 = blockIdx.x * NB;

    // ---------- Phase 0: stage anchors transposed ----------
    {
#pragma unroll
        for (int i = 0; i < 4; i++) {
            int idx = i * 256 + t;          // anchors[p][d]
            an_t[idx & 63][idx >> 6] = anchors[idx];
        }
    }

    // ---------- Phase 1: load x, per-head normalize ----------
    {
        float4 v[NB];
        float  ss[NB];
        const float4* x4 = (const float4*)x;
#pragma unroll
        for (int k = 0; k < NB; k++) {
            v[k] = x4[(size_t)(b0 + k) * 256 + t];
            ss[k] = v[k].x*v[k].x + v[k].y*v[k].y + v[k].z*v[k].z + v[k].w*v[k].w;
        }
#pragma unroll
        for (int k = 0; k < NB; k++) {
#pragma unroll
            for (int off = 8; off; off >>= 1)
                ss[k] += __shfl_xor_sync(0xffffffffu, ss[k], off);
            float inv = 1.0f / (sqrtf(fmaxf(ss[k], 1e-12f)) + 1e-4f);
            float4 w = v[k];
            w.x *= inv; w.y *= inv; w.z *= inv; w.w *= inv;
            ((float4*)xs[k])[t] = w;
        }
    }
    __syncthreads();

    // ---------- Phase 2: poly features (anchors from smem) ----------
    {
        const int h = t >> 4, p = t & 15;
        float acc[NB];
#pragma unroll
        for (int k = 0; k < NB; k++) acc[k] = 0.0f;
#pragma unroll 4
        for (int d4 = 0; d4 < 16; d4++) {
            float ax = an_t[d4 * 4 + 0][p];
            float ay = an_t[d4 * 4 + 1][p];
            float az = an_t[d4 * 4 + 2][p];
            float aw = an_t[d4 * 4 + 3][p];
#pragma unroll
            for (int k = 0; k < NB; k++) {
                float4 xv = ((const float4*)xs[k])[h * 16 + d4];
                acc[k] += xv.x*ax + xv.y*ay + xv.z*az + xv.w*aw;
            }
        }
#pragma unroll
        for (int k = 0; k < NB; k++)
            poly[k][t] = acc[k] * acc[k] * 0.25f;
    }
    __syncthreads();

    // ---------- Phase 3: 7/1 batch-split PRF + interleaved 512B bursts ----------
    {
        const int r  = t >> 7;
        const int h  = (t >> 3) & 15;
        const int m4 = t & 7;
        const float sr = r ? s1 : s0;
        const float cr = r ? c1 : c0;
        const float er = r ? e1 : e0;
        const float4* og = (const float4*)omega + (size_t)((r * 16 + h) * 64) * 8 + m4;
        const size_t obase = r * 8192 + h * 512 + m4 * 4;

        // ---- Batch A: rows 0..6 accumulate ----
        float4 prA[7];
        {
            float4 acc[7];
#pragma unroll
            for (int k = 0; k < 7; k++) acc[k] = make_float4(0.f, 0.f, 0.f, 0.f);
#pragma unroll 4
            for (int d4 = 0; d4 < 16; d4++) {
                float4 o0 = og[(4 * d4 + 0) * 8];
                float4 o1 = og[(4 * d4 + 1) * 8];
                float4 o2 = og[(4 * d4 + 2) * 8];
                float4 o3 = og[(4 * d4 + 3) * 8];
#pragma unroll
                for (int k = 0; k < 7; k++) {
                    float4 xv = ((const float4*)xs[k])[h * 16 + d4];
                    acc[k].x += xv.x*o0.x; acc[k].y += xv.x*o0.y; acc[k].z += xv.x*o0.z; acc[k].w += xv.x*o0.w;
                    acc[k].x += xv.y*o1.x; acc[k].y += xv.y*o1.y; acc[k].z += xv.y*o1.z; acc[k].w += xv.y*o1.w;
                    acc[k].x += xv.z*o2.x; acc[k].y += xv.z*o2.y; acc[k].z += xv.z*o2.z; acc[k].w += xv.z*o2.w;
                    acc[k].x += xv.w*o3.x; acc[k].y += xv.w*o3.y; acc[k].z += xv.w*o3.z; acc[k].w += xv.w*o3.w;
                }
            }
#pragma unroll
            for (int k = 0; k < 7; k++) {
                float4 a = acc[k];
                prA[k].x = er * __expf(fminf(fmaxf(a.x * cr - sr, -20.f), 20.f));
                prA[k].y = er * __expf(fminf(fmaxf(a.y * cr - sr, -20.f), 20.f));
                prA[k].z = er * __expf(fminf(fmaxf(a.z * cr - sr, -20.f), 20.f));
                prA[k].w = er * __expf(fminf(fmaxf(a.w * cr - sr, -20.f), 20.f));
            }
        }

        // ---- Batch B: row 7 accumulate; A's 28 bursts interleaved ----
        {
            float4 acc = make_float4(0.f, 0.f, 0.f, 0.f);

#pragma unroll
            for (int d4 = 0; d4 < 16; d4++) {
                float4 o0 = og[(4 * d4 + 0) * 8];
                float4 o1 = og[(4 * d4 + 1) * 8];
                float4 o2 = og[(4 * d4 + 2) * 8];
                float4 o3 = og[(4 * d4 + 3) * 8];

                float4 xv = ((const float4*)xs[7])[h * 16 + d4];
                acc.x += xv.x*o0.x; acc.y += xv.x*o0.y; acc.z += xv.x*o0.z; acc.w += xv.x*o0.w;
                acc.x += xv.y*o1.x; acc.y += xv.y*o1.y; acc.z += xv.y*o1.z; acc.w += xv.y*o1.w;
                acc.x += xv.z*o2.x; acc.y += xv.z*o2.y; acc.z += xv.z*o2.z; acc.w += xv.z*o2.w;
                acc.x += xv.w*o3.x; acc.y += xv.w*o3.y; acc.z += xv.w*o3.z; acc.w += xv.w*o3.w;

                // burst schedule (compile-time): iters 0..11 -> 2 bursts, 12..15 -> 1
#pragma unroll
                for (int j = 0; j < 2; j++) {
                    if (d4 < 12 || j == 0) {
                        const int bi = (d4 < 12) ? (2 * d4 + j) : (24 + (d4 - 12));  // 0..27
                        const int k  = bi >> 2;          // row 0..6
                        const int p0 = (bi & 3) * 4;
                        float* ob = out + (size_t)(b0 + k) * 16384 + obase;
                        const float* pl = &poly[k][h * 16];
                        float4 pa = prA[k];
#pragma unroll
                        for (int pp = 0; pp < 4; pp++) {
                            float pf = pl[p0 + pp];
                            float4 o;
                            o.x = pf * pa.x; o.y = pf * pa.y; o.z = pf * pa.z; o.w = pf * pa.w;
                            __stcs((float4*)(ob + (p0 + pp) * 32), o);
                        }
                    }
                }
            }

            // exp + tail stores for row 7 (4 bursts exposed)
            float4 pr;
            pr.x = er * __expf(fminf(fmaxf(acc.x * cr - sr, -20.f), 20.f));
            pr.y = er * __expf(fminf(fmaxf(acc.y * cr - sr, -20.f), 20.f));
            pr.z = er * __expf(fminf(fmaxf(acc.z * cr - sr, -20.f), 20.f));
            pr.w = er * __expf(fminf(fmaxf(acc.w * cr - sr, -20.f), 20.f));

            float* ob = out + (size_t)(b0 + 7) * 16384 + obase;
            const float* pl = &poly[7][h * 16];
#pragma unroll
            for (int p = 0; p < 16; p++) {
                float pf = pl[p];
                float4 o;
                o.x = pf * pr.x; o.y = pf * pr.y; o.z = pf * pr.z; o.w = pf * pr.w;
                __stcs((float4*)(ob + p * 32), o);
            }
        }
    }
}

extern "C" void kernel_launch(void* const* d_in, const int* in_sizes, int n_in,
                              void* d_out, int out_size) {
    const float* x       = (const float*)d_in[0];
    const float* omega   = (const float*)d_in[1];
    const float* anchors = (const float*)d_in[2];
    float* out = (float*)d_out;

    const double C   = 2.0 + 1e-6;
    const double rt2 = 1.4142135623730951;
    const double n0d = 2.0 - rt2, n1d = 2.0 + rt2;
    const double w0d = (2.0 + rt2) / 4.0, w1d = (2.0 - rt2) / 4.0;

    float s0 = (float)(n0d / C);
    float s1 = (float)(n1d / C);
    float c0 = sqrtf(2.0f * s0);
    float c1 = sqrtf(2.0f * s1);
    float invSqrtM = 1.0f / sqrtf(32.0f);
    float e0 = sqrtf((float)(w0d / C)) * invSqrtM;
    float e1 = sqrtf((float)(w1d / C)) * invSqrtM;

    slay_kernel<<<8192 / NB, THREADS>>>(x, omega, anchors, out,
                                        s0, s1, c0, c1, e0, e1);
    (void)in_sizes; (void)n_in; (void)out_size;
}